// round 5
// baseline (speedup 1.0000x reference)
#include <cuda_runtime.h>
#include <cuda_fp16.h>
#include <math.h>
#include <stdint.h>

#define B_DIM 512
#define IN_DIM 4096
#define OUT_DIM 11008

// Scratch (allocation-free rule: __device__ global)
__device__ __align__(16) __half g_x16[(size_t)B_DIM * IN_DIM];   // 4 MB fp16 activations

// ---------------------------------------------------------------------------
// x fp32 -> fp16
// ---------------------------------------------------------------------------
__global__ __launch_bounds__(256) void xconv_kernel(const float* __restrict__ x)
{
    size_t i = ((size_t)blockIdx.x * blockDim.x + threadIdx.x) * 4;
    float4 v = *reinterpret_cast<const float4*>(x + i);
    __half2 a = __floats2half2_rn(v.x, v.y);
    __half2 b = __floats2half2_rn(v.z, v.w);
    uint2 o;
    o.x = *reinterpret_cast<unsigned*>(&a);
    o.y = *reinterpret_cast<unsigned*>(&b);
    *reinterpret_cast<uint2*>(&g_x16[i]) = o;
}

// ---------------------------------------------------------------------------
// zero output (required: k-split CTAs accumulate with atomics)
// ---------------------------------------------------------------------------
__global__ __launch_bounds__(256) void zero_out_kernel(float* __restrict__ out)
{
    size_t i = ((size_t)blockIdx.x * blockDim.x + threadIdx.x) * 4;
    *reinterpret_cast<float4*>(out + i) = make_float4(0.f, 0.f, 0.f, 0.f);
}

// ---------------------------------------------------------------------------
// Fused dequant + GEMM.
//   Tile: BM=256 (M half), BN=128, BK=32, K-split 2 (each CTA sums K=2048).
//   Grid: 344 CTAs = 86 N-tiles x 2 M-halves x 2 K-halves.
//   B tile produced in-kernel: LDG raw int32 -> LUT fp16 -> STS.
//   Epilogue: atomicAdd(out, acc*scale [+ bias*scale on kh==0]).
// ---------------------------------------------------------------------------
#define BM 256
#define BN 128
#define BK 32
#define KSPL 2
#define KPER (IN_DIM / KSPL)      // 2048
#define NIT (KPER / BK)           // 64
#define ASTR 40                   // smem row stride in halves (32 + 8 skew)
#define A_STAGE (BM * ASTR)       // halves
#define B_STAGE (BN * ASTR)
// dynamic smem layout: [0,1024): lut u32[256]; [1024,+2*A_STAGE*2): sA; then sB
#define SM_A_OFF 1024
#define SM_B_OFF (SM_A_OFF + 2 * A_STAGE * 2)
#define SM_TOTAL (SM_B_OFF + 2 * B_STAGE * 2)

static __device__ __forceinline__ void cp16(uint32_t dst, const void* src) {
    asm volatile("cp.async.cg.shared.global [%0], [%1], 16;\n" :: "r"(dst), "l"(src));
}
static __device__ __forceinline__ void cp_commit() {
    asm volatile("cp.async.commit_group;\n" ::: "memory");
}
static __device__ __forceinline__ void cp_wait0() {
    asm volatile("cp.async.wait_group 0;\n" ::: "memory");
}
static __device__ __forceinline__ void ldm_x4(unsigned& r0, unsigned& r1, unsigned& r2,
                                              unsigned& r3, uint32_t a) {
    asm volatile("ldmatrix.sync.aligned.m8n8.x4.shared.b16 {%0,%1,%2,%3}, [%4];\n"
                 : "=r"(r0), "=r"(r1), "=r"(r2), "=r"(r3) : "r"(a));
}
static __device__ __forceinline__ void mma16816(float* d, const unsigned* a,
                                                const unsigned* b) {
    asm volatile(
        "mma.sync.aligned.m16n8k16.row.col.f32.f16.f16.f32 "
        "{%0,%1,%2,%3}, {%4,%5,%6,%7}, {%8,%9}, {%0,%1,%2,%3};\n"
        : "+f"(d[0]), "+f"(d[1]), "+f"(d[2]), "+f"(d[3])
        : "r"(a[0]), "r"(a[1]), "r"(a[2]), "r"(a[3]), "r"(b[0]), "r"(b[1]));
}

__global__ __launch_bounds__(256, 1) void fused_gemm(
    const int* __restrict__ stored, const int* __restrict__ sign,
    const float* __restrict__ log_min_p, const float* __restrict__ log_max_p,
    const float* __restrict__ scale, const float* __restrict__ bias,
    float* __restrict__ out)
{
    extern __shared__ __align__(16) char smem[];
    unsigned* lut = reinterpret_cast<unsigned*>(smem);
    const uint32_t smem_u = (uint32_t)__cvta_generic_to_shared(smem);
    const uint32_t sA_u = smem_u + SM_A_OFF;
    const uint32_t sB_u = smem_u + SM_B_OFF;

    const int tid = threadIdx.x;
    const int bid = blockIdx.x;
    const int bn = bid >> 2;
    const int mh = bid & 1;
    const int kh = (bid >> 1) & 1;
    const int kbase = kh * KPER;

    // Build fp16 LUT (256 entries)
    {
        float lmin = *log_min_p;
        float lmax = *log_max_p;
        float nrm = (255.0f - (float)tid) * (1.0f / 254.0f);
        lut[tid] = (unsigned)__half_as_ushort(__float2half(expf(lmin + nrm * (lmax - lmin))));
    }

    const int warp = tid >> 5;
    const int lane = tid & 31;
    const int wm = warp >> 1;   // 0..3 -> 64 M rows each
    const int wn = warp & 1;    // 0..1 -> 64 N cols each

    const __half* gA = g_x16 + (size_t)(mh * BM) * IN_DIM + kbase;
    const size_t wrow0 = (size_t)bn * BN;

    float acc[4][8][4];
#pragma unroll
    for (int mi = 0; mi < 4; mi++)
#pragma unroll
        for (int ni = 0; ni < 8; ni++)
#pragma unroll
            for (int r = 0; r < 4; r++) acc[mi][ni][r] = 0.0f;

    // ---- raw B loader: 128x32 ints. thread -> row tid>>1, 16 elems (2 thr/row).
    const int brow = tid >> 1;
    const int bcol0 = (tid & 1) * 16;
    const size_t braw_off = (wrow0 + brow) * IN_DIM + kbase + bcol0;
    int4 rs[4], rg[4];

    auto ldg_raw = [&](int it) {
        const int4* ps = reinterpret_cast<const int4*>(stored + braw_off + it * BK);
        const int4* pg = reinterpret_cast<const int4*>(sign + braw_off + it * BK);
#pragma unroll
        for (int q = 0; q < 4; q++) rs[q] = ps[q];
#pragma unroll
        for (int q = 0; q < 4; q++) rg[q] = pg[q];
    };

    // each int4 (4 raw ints) -> 4 halves = 8 bytes; stride q*8 (NOT q*16).
    auto sts_deq = [&](int s) {
        uint32_t dst = sB_u + (uint32_t)(s * B_STAGE + brow * ASTR + bcol0) * 2;
#pragma unroll
        for (int q = 0; q < 4; q++) {
            int sv[4] = {rs[q].x, rs[q].y, rs[q].z, rs[q].w};
            int gv[4] = {rg[q].x, rg[q].y, rg[q].z, rg[q].w};
            unsigned h[4];
#pragma unroll
            for (int j = 0; j < 4; j++)
                h[j] = lut[sv[j] & 0xFF] ^ ((((unsigned)gv[j]) >> 16) & 0x8000u);
            unsigned p0 = h[0] | (h[1] << 16);
            unsigned p1 = h[2] | (h[3] << 16);
            asm volatile("st.shared.v2.b32 [%0], {%1,%2};\n"
                         :: "r"(dst + q * 8), "r"(p0), "r"(p1) : "memory");
        }
    };

    // ---- A loader (cp.async): 256x32 halves, 1024 16B chunks, 4/thread
    auto load_A = [&](int s, int it) {
#pragma unroll
        for (int i = 0; i < 4; i++) {
            int id = tid + i * 256;
            int row = id >> 2;
            int c = id & 3;
            cp16(sA_u + (uint32_t)(s * A_STAGE + row * ASTR + c * 8) * 2,
                 gA + (size_t)row * IN_DIM + it * BK + c * 8);
        }
    };

    auto compute = [&](int s) {
#pragma unroll
        for (int ks = 0; ks < 2; ks++) {
            unsigned afr[4][4];
#pragma unroll
            for (int mi = 0; mi < 4; mi++) {
                uint32_t p = sA_u + (uint32_t)(s * A_STAGE +
                             (wm * 64 + mi * 16 + (lane & 15)) * ASTR +
                             ks * 16 + (lane >> 4) * 8) * 2;
                ldm_x4(afr[mi][0], afr[mi][1], afr[mi][2], afr[mi][3], p);
            }
            unsigned bfr[8][2];
#pragma unroll
            for (int nj = 0; nj < 4; nj++) {
                uint32_t p = sB_u + (uint32_t)(s * B_STAGE +
                             (wn * 64 + nj * 16 + ((lane >> 4) & 1) * 8 + (lane & 7)) * ASTR +
                             ks * 16 + ((lane >> 3) & 1) * 8) * 2;
                unsigned r0, r1, r2, r3;
                ldm_x4(r0, r1, r2, r3, p);
                bfr[2 * nj + 0][0] = r0;
                bfr[2 * nj + 0][1] = r1;
                bfr[2 * nj + 1][0] = r2;
                bfr[2 * nj + 1][1] = r3;
            }
#pragma unroll
            for (int mi = 0; mi < 4; mi++)
#pragma unroll
                for (int ni = 0; ni < 8; ni++)
                    mma16816(acc[mi][ni], afr[mi], bfr[ni]);
        }
    };

    // ---- prologue
    ldg_raw(0);
    load_A(0, 0);
    cp_commit();
    __syncthreads();          // lut ready before sts_deq reads it
    sts_deq(0);
    cp_wait0();
    __syncthreads();          // stage 0 fully resident

    // ---- main loop
    for (int t = 0; t < NIT; t++) {
        const int s0 = t & 1;
        const int s1 = s0 ^ 1;
        if (t + 1 < NIT) {
            ldg_raw(t + 1);
            load_A(s1, t + 1);
        }
        cp_commit();
        compute(s0);
        if (t + 1 < NIT) sts_deq(s1);
        cp_wait0();
        __syncthreads();
    }

    // ---- epilogue: atomicAdd(out, acc*scale (+bias*scale once, on kh==0))
    const int row0 = mh * BM + wm * 64;
    const int col0 = bn * BN + wn * 64;
    const int cl = (lane & 3) * 2;
    const int rl = lane >> 2;

#pragma unroll
    for (int ni = 0; ni < 8; ni++) {
        const int c = col0 + ni * 8 + cl;
        const float s0 = scale[c];
        const float s1 = scale[c + 1];
        const float b0 = (kh == 0) ? bias[c] * s0 : 0.0f;
        const float b1 = (kh == 0) ? bias[c + 1] * s1 : 0.0f;
#pragma unroll
        for (int mi = 0; mi < 4; mi++) {
            const int r = row0 + mi * 16 + rl;
            float* p0 = out + (size_t)r * OUT_DIM + c;
            float* p1 = out + (size_t)(r + 8) * OUT_DIM + c;
            atomicAdd(p0 + 0, acc[mi][ni][0] * s0 + b0);
            atomicAdd(p0 + 1, acc[mi][ni][1] * s1 + b1);
            atomicAdd(p1 + 0, acc[mi][ni][2] * s0 + b0);
            atomicAdd(p1 + 1, acc[mi][ni][3] * s1 + b1);
        }
    }
}

// ---------------------------------------------------------------------------
// Launch
// ---------------------------------------------------------------------------
extern "C" void kernel_launch(void* const* d_in, const int* in_sizes, int n_in,
                              void* d_out, int out_size)
{
    const float* x       = (const float*)d_in[0];
    const int*   stored  = (const int*)d_in[1];
    const int*   sign    = (const int*)d_in[2];
    const float* log_min = (const float*)d_in[3];
    const float* log_max = (const float*)d_in[4];
    const float* scale   = (const float*)d_in[5];
    const float* bias    = (const float*)d_in[6];
    float* out = (float*)d_out;

    cudaFuncSetAttribute(fused_gemm, cudaFuncAttributeMaxDynamicSharedMemorySize,
                         SM_TOTAL);

    // x fp32 -> fp16 (2048 blocks * 256 thr * 4 elems = 2,097,152)
    xconv_kernel<<<2048, 256>>>(x);
    // zero out (512*11008/4/256 = 5504 blocks)
    zero_out_kernel<<<5504, 256>>>(out);
    // fused dequant+GEMM: 86 N-tiles x 2 M-halves x 2 K-halves
    fused_gemm<<<86 * 4, 256, SM_TOTAL>>>(stored, sign, log_min, log_max,
                                          scale, bias, out);
}

// round 8
// speedup vs baseline: 1.3738x; 1.3738x over previous
#include <cuda_runtime.h>
#include <cuda_fp16.h>
#include <math.h>
#include <stdint.h>

#define B_DIM 512
#define IN_DIM 4096
#define OUT_DIM 11008

// Scratch (allocation-free rule: __device__ globals)
__device__ __align__(16) __half g_W16[(size_t)OUT_DIM * IN_DIM];   // 90 MB fp16 weights
__device__ __align__(16) __half g_x16[(size_t)B_DIM * IN_DIM];     // 4 MB fp16 activations

// ---------------------------------------------------------------------------
// Kernel 1: dequantize QINS weights -> fp16 via 256-entry LUT (DRAM roofline)
// ---------------------------------------------------------------------------
__global__ __launch_bounds__(256) void dequant_kernel(
    const int* __restrict__ stored, const int* __restrict__ sign,
    const float* __restrict__ log_min_p, const float* __restrict__ log_max_p)
{
    __shared__ unsigned short lut[256];
    int t = threadIdx.x;
    if (t < 256) {
        float lmin = *log_min_p;
        float lmax = *log_max_p;
        float nrm = (255.0f - (float)t) * (1.0f / 254.0f);
        lut[t] = __half_as_ushort(__float2half(expf(lmin + nrm * (lmax - lmin))));
    }
    __syncthreads();

    size_t base = ((size_t)blockIdx.x * blockDim.x + threadIdx.x) * 8;
    const int4* st4 = reinterpret_cast<const int4*>(stored + base);
    const int4* sg4 = reinterpret_cast<const int4*>(sign + base);
    int4 s0 = st4[0];
    int4 s1 = st4[1];
    int4 g0 = sg4[0];
    int4 g1 = sg4[1];

    unsigned h[8];
    {
        const int sv[8] = {s0.x, s0.y, s0.z, s0.w, s1.x, s1.y, s1.z, s1.w};
        const int gv[8] = {g0.x, g0.y, g0.z, g0.w, g1.x, g1.y, g1.z, g1.w};
#pragma unroll
        for (int i = 0; i < 8; i++) {
            unsigned hb = (unsigned)lut[sv[i] & 0xFF];
            hb ^= ((((unsigned)gv[i]) >> 16) & 0x8000u);
            h[i] = hb;
        }
    }
    uint4 outv;
    outv.x = h[0] | (h[1] << 16);
    outv.y = h[2] | (h[3] << 16);
    outv.z = h[4] | (h[5] << 16);
    outv.w = h[6] | (h[7] << 16);
    *reinterpret_cast<uint4*>(&g_W16[base]) = outv;
}

// ---------------------------------------------------------------------------
// Kernel 2: x fp32 -> fp16
// ---------------------------------------------------------------------------
__global__ __launch_bounds__(256) void xconv_kernel(const float* __restrict__ x)
{
    size_t i = ((size_t)blockIdx.x * blockDim.x + threadIdx.x) * 4;
    float4 v = *reinterpret_cast<const float4*>(x + i);
    __half2 a = __floats2half2_rn(v.x, v.y);
    __half2 b = __floats2half2_rn(v.z, v.w);
    uint2 o;
    o.x = *reinterpret_cast<unsigned*>(&a);
    o.y = *reinterpret_cast<unsigned*>(&b);
    *reinterpret_cast<uint2*>(&g_x16[i]) = o;
}

// ---------------------------------------------------------------------------
// Kernel 3: GEMM. BM=128, BN=128, BK=64, 3-stage cp.async, 2 CTAs/SM.
//   8 warps (2 M x 4 N), warp tile 64x32, acc = 64 regs.
// ---------------------------------------------------------------------------
#define BM 128
#define BN 128
#define BK 64
#define NST 3
#define NIT (IN_DIM / BK)          // 64
#define BSTRIDE 72                 // halves: 64 + 8 skew (144B rows, conflict-free)
#define A_STAGE (BM * BSTRIDE)     // halves
#define B_STAGE (BN * BSTRIDE)
#define STAGE_HALVES (A_STAGE + B_STAGE)
#define SM_TOTAL (NST * STAGE_HALVES * 2)   // bytes = 110,592

static __device__ __forceinline__ void cp16(uint32_t dst, const void* src) {
    asm volatile("cp.async.cg.shared.global [%0], [%1], 16;\n" :: "r"(dst), "l"(src));
}
static __device__ __forceinline__ void cp_commit() {
    asm volatile("cp.async.commit_group;\n" ::: "memory");
}
template <int N>
static __device__ __forceinline__ void cp_wait() {
    asm volatile("cp.async.wait_group %0;\n" :: "n"(N) : "memory");
}
static __device__ __forceinline__ void ldm_x4(unsigned& r0, unsigned& r1, unsigned& r2,
                                              unsigned& r3, uint32_t a) {
    asm volatile("ldmatrix.sync.aligned.m8n8.x4.shared.b16 {%0,%1,%2,%3}, [%4];\n"
                 : "=r"(r0), "=r"(r1), "=r"(r2), "=r"(r3) : "r"(a));
}
static __device__ __forceinline__ void mma16816(float* d, const unsigned* a,
                                                const unsigned* b) {
    asm volatile(
        "mma.sync.aligned.m16n8k16.row.col.f32.f16.f16.f32 "
        "{%0,%1,%2,%3}, {%4,%5,%6,%7}, {%8,%9}, {%0,%1,%2,%3};\n"
        : "+f"(d[0]), "+f"(d[1]), "+f"(d[2]), "+f"(d[3])
        : "r"(a[0]), "r"(a[1]), "r"(a[2]), "r"(a[3]), "r"(b[0]), "r"(b[1]));
}

__global__ __launch_bounds__(256, 2) void gemm_kernel(
    const float* __restrict__ bias, const float* __restrict__ scale,
    float* __restrict__ out)
{
    extern __shared__ __align__(16) __half smem[];
    const uint32_t smem_u = (uint32_t)__cvta_generic_to_shared(smem);

    const int tid = threadIdx.x;
    const int bm = blockIdx.x;   // 0..3   (M) -- consecutive bids share W16 (L2 dedup)
    const int bn = blockIdx.y;   // 0..85  (N)
    const int warp = tid >> 5;
    const int lane = tid & 31;
    const int wm = warp >> 2;    // 0..1  (64 M rows each)
    const int wn = warp & 3;     // 0..3  (32 N cols each)

    const __half* gA = g_x16 + (size_t)(bm * BM) * IN_DIM;
    const __half* gB = g_W16 + (size_t)(bn * BN) * IN_DIM;

    float acc[4][4][4];
#pragma unroll
    for (int mi = 0; mi < 4; mi++)
#pragma unroll
        for (int ni = 0; ni < 4; ni++)
#pragma unroll
            for (int r = 0; r < 4; r++) acc[mi][ni][r] = 0.0f;

    // loader: per stage, A and B each 128 rows x 64 halves = 1024 16B chunks
    auto load_tile = [&](int s, int kt) {
        const uint32_t a0 = smem_u + (uint32_t)(s * STAGE_HALVES) * 2;
        const uint32_t b0 = a0 + (uint32_t)A_STAGE * 2;
        const int k0 = kt * BK;
#pragma unroll
        for (int i = 0; i < 4; i++) {
            int id = tid + i * 256;      // 0..1023
            int row = id >> 3;
            int c = id & 7;
            uint32_t so = (uint32_t)(row * BSTRIDE + c * 8) * 2;
            size_t go = (size_t)row * IN_DIM + k0 + c * 8;
            cp16(a0 + so, gA + go);
            cp16(b0 + so, gB + go);
        }
    };

    load_tile(0, 0);
    cp_commit();
    load_tile(1, 1);
    cp_commit();
    load_tile(2, 2);
    cp_commit();

    for (int t = 0; t < NIT; t++) {
        cp_wait<2>();
        __syncthreads();                 // stage t%3 resident
        const int s = t % NST;
        const uint32_t aB = smem_u + (uint32_t)(s * STAGE_HALVES) * 2;
        const uint32_t bB = aB + (uint32_t)A_STAGE * 2;

#pragma unroll
        for (int ks = 0; ks < 4; ks++) {
            unsigned afr[4][4];
#pragma unroll
            for (int mi = 0; mi < 4; mi++) {
                uint32_t p = aB + (uint32_t)((wm * 64 + mi * 16 + (lane & 15)) * BSTRIDE +
                                             ks * 16 + (lane >> 4) * 8) * 2;
                ldm_x4(afr[mi][0], afr[mi][1], afr[mi][2], afr[mi][3], p);
            }
            unsigned bfr[4][2];
#pragma unroll
            for (int nj = 0; nj < 2; nj++) {
                uint32_t p = bB + (uint32_t)((wn * 32 + nj * 16 + ((lane >> 4) & 1) * 8 +
                                              (lane & 7)) * BSTRIDE +
                                             ks * 16 + ((lane >> 3) & 1) * 8) * 2;
                unsigned r0, r1, r2, r3;
                ldm_x4(r0, r1, r2, r3, p);
                bfr[2 * nj + 0][0] = r0;
                bfr[2 * nj + 0][1] = r1;
                bfr[2 * nj + 1][0] = r2;
                bfr[2 * nj + 1][1] = r3;
            }
#pragma unroll
            for (int mi = 0; mi < 4; mi++)
#pragma unroll
                for (int ni = 0; ni < 4; ni++)
                    mma16816(acc[mi][ni], afr[mi], bfr[ni]);
        }

        __syncthreads();                 // stage s free for reload
        if (t + 3 < NIT) load_tile(s, t + 3);
        cp_commit();                     // uniform group count per iter
    }

    // Epilogue: out = acc*scale + bias*scale (plain stores)
    const int row0 = bm * BM + wm * 64;
    const int col0 = bn * BN + wn * 32;
    const int cl = (lane & 3) * 2;
    const int rl = lane >> 2;

#pragma unroll
    for (int ni = 0; ni < 4; ni++) {
        const int c = col0 + ni * 8 + cl;
        const float s0 = scale[c];
        const float s1 = scale[c + 1];
        const float b0 = bias[c] * s0;
        const float b1 = bias[c + 1] * s1;
#pragma unroll
        for (int mi = 0; mi < 4; mi++) {
            const int r = row0 + mi * 16 + rl;
            float2 v0, v1;
            v0.x = acc[mi][ni][0] * s0 + b0;
            v0.y = acc[mi][ni][1] * s1 + b1;
            v1.x = acc[mi][ni][2] * s0 + b0;
            v1.y = acc[mi][ni][3] * s1 + b1;
            *reinterpret_cast<float2*>(&out[(size_t)r * OUT_DIM + c]) = v0;
            *reinterpret_cast<float2*>(&out[(size_t)(r + 8) * OUT_DIM + c]) = v1;
        }
    }
}

// ---------------------------------------------------------------------------
// Launch
// ---------------------------------------------------------------------------
extern "C" void kernel_launch(void* const* d_in, const int* in_sizes, int n_in,
                              void* d_out, int out_size)
{
    const float* x       = (const float*)d_in[0];
    const int*   stored  = (const int*)d_in[1];
    const int*   sign    = (const int*)d_in[2];
    const float* log_min = (const float*)d_in[3];
    const float* log_max = (const float*)d_in[4];
    const float* scale   = (const float*)d_in[5];
    const float* bias    = (const float*)d_in[6];
    float* out = (float*)d_out;

    cudaFuncSetAttribute(gemm_kernel, cudaFuncAttributeMaxDynamicSharedMemorySize,
                         SM_TOTAL);

    dequant_kernel<<<22016, 256>>>(stored, sign, log_min, log_max);
    xconv_kernel<<<2048, 256>>>(x);

    dim3 grid(4, 86);   // (M tiles, N tiles); bid-adjacent M tiles share W16 in L2
    gemm_kernel<<<grid, 256, SM_TOTAL>>>(bias, scale, out);
}